// round 16
// baseline (speedup 1.0000x reference)
#include <cuda_runtime.h>
#include <cuda_fp16.h>
#include <math.h>

#define NB   8
#define DC   32
#define HS   512
#define WSZ  512
#define HH   256
#define WW   256
#define KW   7
#define KK2  49
#define HID  64
#define AA   256
#define NPIX 65536          // HH*WW
#define PADW 262
#define PPIX (PADW*PADW)    // 68644  (fp16 activation pad)
#define UROW 264
#define UPP  (262*UROW)     // u' plane: 262 rows x 264 cols

typedef unsigned long long ull;

// ---------------- scratch (device globals; zero-initialized by CUDA) -------
// Pads of g_u / g_t0 / g_t1 are NEVER written -> stay zero.
__device__ __align__(256) float g_x  [NB * DC  * NPIX];
__device__ __align__(256) float g_x2 [NB * DC  * NPIX];   // x2 planar
__device__ __align__(256) float g_u  [NB * KK2 * UPP];
__device__ __align__(256) float g_lang[NB * KK2];
__device__ __align__(256) __half g_h1h[(size_t)NB * NPIX * HID]; // h3 rows fp16

// transposed zero-padded activations: [n][pixpad][64] fp16
__device__ __align__(256) __half g_t0[(size_t)NB * PPIX * 64];
__device__ __align__(256) __half g_t1[(size_t)NB * PPIX * 64];

// conv weights: [tap][oc][64] fp16
__device__ __align__(256) __half g_w3m[9 * 64 * 64];
__device__ __align__(256) __half g_w1m[9 * 64 * 64];

// packed f32x2 weights for pointwise kernels
__device__ __align__(16) ull g_wi[DC * 32];
__device__ __align__(16) ull g_wo[HID * 16];
__device__ __align__(16) ull g_wk[DC * 25];

// ---------------- f32x2 helpers -------------------------------------------
__device__ __forceinline__ ull pack2(float lo, float hi) {
    ull r; asm("mov.b64 %0, {%1, %2};" : "=l"(r) : "f"(lo), "f"(hi)); return r;
}
__device__ __forceinline__ void unpack2(ull v, float& lo, float& hi) {
    asm("mov.b64 {%0, %1}, %2;" : "=f"(lo), "=f"(hi) : "l"(v));
}
__device__ __forceinline__ void ffma2(ull& d, ull a, ull b) {
    asm("fma.rn.f32x2 %0, %1, %2, %0;" : "+l"(d) : "l"(a), "l"(b));
}
__device__ __forceinline__ float fexp(float x) {
    float t  = fmaxf(x * 1.44269504f, -120.f);
    float rv = rintf(t);
    int   e  = (int)rv;
    float f  = t - rv;
    float p  = 1.33335581e-3f;
    p = fmaf(p, f, 9.61812910e-3f);
    p = fmaf(p, f, 5.55041087e-2f);
    p = fmaf(p, f, 2.40226507e-1f);
    p = fmaf(p, f, 6.93147181e-1f);
    p = fmaf(p, f, 1.0f);
    return __int_as_float(__float_as_int(p) + (e << 23));
}

// ---------------- tensor-core + async helpers (sm_80 baseline) -------------
__device__ __forceinline__ unsigned smem_u32(const void* p) {
    unsigned a;
    asm("{ .reg .u64 t; cvta.to.shared.u64 t, %1; cvt.u32.u64 %0, t; }"
        : "=r"(a) : "l"(p));
    return a;
}
__device__ __forceinline__ void ldsm4(unsigned& r0, unsigned& r1,
                                      unsigned& r2, unsigned& r3, unsigned addr) {
    asm volatile("ldmatrix.sync.aligned.m8n8.x4.shared.b16 {%0,%1,%2,%3}, [%4];"
                 : "=r"(r0), "=r"(r1), "=r"(r2), "=r"(r3) : "r"(addr));
}
__device__ __forceinline__ void mma16816(float* c, const unsigned* a,
                                         unsigned b0, unsigned b1) {
    asm volatile(
        "mma.sync.aligned.m16n8k16.row.col.f32.f16.f16.f32 "
        "{%0,%1,%2,%3}, {%4,%5,%6,%7}, {%8,%9}, {%0,%1,%2,%3};"
        : "+f"(c[0]), "+f"(c[1]), "+f"(c[2]), "+f"(c[3])
        : "r"(a[0]), "r"(a[1]), "r"(a[2]), "r"(a[3]), "r"(b0), "r"(b1));
}
__device__ __forceinline__ void cpasync16(unsigned dst, const void* src) {
    asm volatile("cp.async.ca.shared.global [%0], [%1], 16;"
                 :: "r"(dst), "l"(src));
}
#define CP_COMMIT() asm volatile("cp.async.commit_group;" ::: "memory")
#define CP_WAIT0()  asm volatile("cp.async.wait_group 0;" ::: "memory")

// ---------------- K0: weight packing only ----------------------------------
__global__ void k_prep(const float* __restrict__ w_d3, const float* __restrict__ w_d1,
                       const float* __restrict__ w_in, const float* __restrict__ w_out,
                       const float* __restrict__ w_k) {
    int i = blockIdx.x * 256 + threadIdx.x;
    if (i < 36864) {
        int ic = i & 63, oc = (i >> 6) & 63, tap = i >> 12;
        g_w3m[i] = __float2half_rn(w_d3[((size_t)oc * HID + ic) * 9 + tap]);
    } else if (i < 73728) {
        int q = i - 36864;
        int ic = q & 63, oc = (q >> 6) & 63, tap = q >> 12;
        g_w1m[q] = __float2half_rn(w_d1[((size_t)oc * HID + ic) * 9 + tap]);
    } else if (i < 74752) {
        int q = i - 73728; int c = q >> 5, j = q & 31;
        g_wi[q] = pack2(w_in[(2*j)*DC + c], w_in[(2*j+1)*DC + c]);
    } else if (i < 75776) {
        int q = i - 74752; int ic = q >> 4, cc = q & 15;
        g_wo[q] = pack2(w_out[(2*cc)*HID + ic], w_out[(2*cc+1)*HID + ic]);
    } else if (i < 76576) {
        int q = i - 75776; int c = q / 25, kk = q % 25;
        float w1v = (2*kk + 1 < KK2) ? w_k[(2*kk+1)*DC + c] : 0.f;
        g_wk[q] = pack2(w_k[(2*kk)*DC + c], w1v);
    }
}

// ---------------- K1: FUSED 2x2 max pool + conv1x1 32->64 + relu ------------
__global__ __launch_bounds__(256, 2) void k_pool_in(const float* __restrict__ sem,
                                                    const float* __restrict__ b) {
    __shared__ ull   sw2[DC * 32];
    __shared__ float sb[HID];
    for (int i = threadIdx.x; i < DC * 32; i += 256) sw2[i] = g_wi[i];
    if (threadIdx.x < HID) sb[threadIdx.x] = b[threadIdx.x];
    __syncthreads();

    int p   = blockIdx.x * 256 + threadIdx.x;
    int n   = p >> 16;
    int pix = p & (NPIX - 1);
    int y = pix >> 8, x = pix & 255;

    float xv[DC];
    const float* base = sem + ((size_t)n * DC) * HS * WSZ
                        + (size_t)(2 * y) * WSZ + 2 * x;
#pragma unroll
    for (int c = 0; c < DC; c++) {
        const float2* r0 = (const float2*)(base + (size_t)c * HS * WSZ);
        const float2* r1 = (const float2*)(base + (size_t)c * HS * WSZ + WSZ);
        float2 a = r0[0];
        float2 bb = r1[0];
        xv[c] = fmaxf(fmaxf(a.x, a.y), fmaxf(bb.x, bb.y));
    }

    float* xo = g_x + (size_t)n * DC * NPIX + pix;
#pragma unroll
    for (int c = 0; c < DC; c++) xo[(size_t)c * NPIX] = xv[c];

    uint4* d4 = (uint4*)(g_t0 + ((size_t)n * PPIX + (size_t)(y + 3) * PADW + (x + 3)) * 64);
#pragma unroll
    for (int half = 0; half < 2; half++) {
        int off = half * 16;
        ull acc[16];
#pragma unroll
        for (int j = 0; j < 16; j++)
            acc[j] = pack2(sb[half*32 + 2*j], sb[half*32 + 2*j + 1]);
#pragma unroll
        for (int c = 0; c < DC; c++) {
            ull xp = pack2(xv[c], xv[c]);
#pragma unroll
            for (int j = 0; j < 16; j++) ffma2(acc[j], sw2[c*32 + off + j], xp);
        }
        unsigned hv[16];
#pragma unroll
        for (int j = 0; j < 16; j++) {
            float v0, v1; unpack2(acc[j], v0, v1);
            __half2 hh = __floats2half2_rn(fmaxf(v0, 0.f), fmaxf(v1, 0.f));
            hv[j] = *(unsigned*)&hh;
        }
#pragma unroll
        for (int q = 0; q < 4; q++)
            d4[half*4 + q] = make_uint4(hv[4*q], hv[4*q+1], hv[4*q+2], hv[4*q+3]);
    }
}

// ---------------- conv3x3 mainloop (fp16 K=64, 32x32 warp tiles) ------------
#define ASLOT   17152
#define WOFF2   34304
#define CSM_B2  50688
#define CSMEM2  50944

template <int DIL>
__device__ __forceinline__ void conv_main(const __half* __restrict__ tin,
                                          const __half* __restrict__ wgt,
                                          char* smem, unsigned sbase,
                                          int y, int x0, size_t nb) {
    constexpr int NSPH = 128 + 2 * DIL;
    int tid = threadIdx.x, lane = tid & 31, w = tid >> 5;
    int wm = w & 3, wn = w >> 2;           // 4 x 2 warp grid

    auto stage_A = [&](int ky, int slot, int part) {
        int ypad = y + (ky - 1) * DIL + 3;
        const __half* src =
            tin + (nb + (size_t)ypad * PADW + (3 + x0 - DIL)) * 64;
        int lo = (part == 1) ? (NSPH * 8) / 2 : 0;
        int hi = (part == 0) ? (NSPH * 8) / 2 : NSPH * 8;
        for (int i = lo + tid; i < hi; i += 256) {
            int sp = i >> 3, seg = i & 7;
            unsigned rel = sp * 128 + ((seg << 4) ^ ((sp & 7) << 4));
            cpasync16(sbase + slot * ASLOT + rel, src + sp * 64 + seg * 8);
        }
    };
    auto stage_W = [&](int tap, int slot) {
        const __half* ws = wgt + (size_t)tap * 64 * 64;
#pragma unroll
        for (int k = 0; k < 2; k++) {
            int i = tid + k * 256;
            int oc = i >> 3, seg = i & 7;
            unsigned rel = oc * 128 + ((seg << 4) ^ ((oc & 7) << 4));
            cpasync16(sbase + WOFF2 + slot * 8192 + rel, ws + oc * 64 + seg * 8);
        }
    };

    float acc[2][4][4];
#pragma unroll
    for (int a = 0; a < 2; a++)
#pragma unroll
        for (int b2 = 0; b2 < 4; b2++)
#pragma unroll
            for (int c = 0; c < 4; c++) acc[a][b2][c] = 0.f;

    const int akoff = ((lane >> 4) & 1) << 4;
    const int bkoff = ((lane >> 3) & 1) << 4;

    stage_A(0, 0, 2);
    stage_W(0, 0);
    CP_COMMIT();
    CP_WAIT0();
    __syncthreads();

#pragma unroll
    for (int t = 0; t < 9; t++) {
        const int ky = t / 3, kx = t % 3;
        const int wslot = t & 1;
        const int aslot = ky & 1;

        if (t < 8) {
            stage_W(t + 1, wslot ^ 1);
            if (kx < 2 && ky < 2) stage_A(ky + 1, aslot ^ 1, kx);
            CP_COMMIT();
        }

        unsigned arow[2], arx[2];
#pragma unroll
        for (int mt = 0; mt < 2; mt++) {
            int px = wm * 32 + mt * 16 + ((lane >> 3) & 1) * 8 + (lane & 7);
            int sp = px + kx * DIL;
            arow[mt] = sbase + aslot * ASLOT + sp * 128;
            arx[mt]  = (sp & 7) << 4;
        }
        unsigned Wb = sbase + WOFF2 + wslot * 8192;
        unsigned brow[2], brx[2];
#pragma unroll
        for (int j = 0; j < 2; j++) {
            int ocb = wn * 32 + j * 16 + ((lane >> 4) & 1) * 8 + (lane & 7);
            brow[j] = Wb + ocb * 128;
            brx[j]  = (ocb & 7) << 4;
        }

#pragma unroll
        for (int kc = 0; kc < 4; kc++) {
            unsigned a[2][4];
#pragma unroll
            for (int mt = 0; mt < 2; mt++)
                ldsm4(a[mt][0], a[mt][1], a[mt][2], a[mt][3],
                      arow[mt] + (unsigned)((kc * 32 + akoff) ^ arx[mt]));
            unsigned b[2][4];
#pragma unroll
            for (int j = 0; j < 2; j++)
                ldsm4(b[j][0], b[j][1], b[j][2], b[j][3],
                      brow[j] + (unsigned)((kc * 32 + bkoff) ^ brx[j]));
#pragma unroll
            for (int mt = 0; mt < 2; mt++)
#pragma unroll
                for (int nt = 0; nt < 4; nt++)
                    mma16816(acc[mt][nt], a[mt],
                             b[nt >> 1][(nt & 1) * 2],
                             b[nt >> 1][(nt & 1) * 2 + 1]);
        }

        CP_WAIT0();
        __syncthreads();
    }

    float* sd = (float*)smem;
#pragma unroll
    for (int mt = 0; mt < 2; mt++)
#pragma unroll
        for (int nt = 0; nt < 4; nt++)
#pragma unroll
            for (int c = 0; c < 4; c++) {
                int px = wm * 32 + mt * 16 + (lane >> 2) + ((c >> 1) & 1) * 8;
                int oc = wn * 32 + nt * 8 + 2 * (lane & 3) + (c & 1);
                sd[px * 65 + oc] = acc[mt][nt][c];
            }
    __syncthreads();
}

// ---------------- K2: conv dil=3  t0 -> t1 (fp16) ---------------------------
__global__ __launch_bounds__(256, 3) void k_conv3(const float* __restrict__ bg) {
    extern __shared__ char smem[];
    unsigned sbase = smem_u32(smem);
    float* sbias = (float*)(smem + CSM_B2);
    int tid = threadIdx.x;
    int bx = blockIdx.x;
    int y  = bx >> 1;
    int x0 = (bx & 1) << 7;
    int n  = blockIdx.y;
    if (tid < 64) sbias[tid] = bg[tid];
    const size_t nb = (size_t)n * PPIX;

    conv_main<3>(g_t0, g_w3m, smem, sbase, y, x0, nb);

    const float* sd = (const float*)smem;
    int px = tid >> 1, h = tid & 1;
    const float* r = sd + px * 65;
    unsigned hv[16];
#pragma unroll
    for (int j = 0; j < 16; j++) {
        int oc = h * 32 + 2 * j;
        __half2 hh = __floats2half2_rn(fmaxf(r[oc]     + sbias[oc],     0.f),
                                       fmaxf(r[oc + 1] + sbias[oc + 1], 0.f));
        hv[j] = *(unsigned*)&hh;
    }
    uint4* d4 = (uint4*)(g_t1 + (nb + (size_t)(y + 3) * PADW + (x0 + px + 3)) * 64);
#pragma unroll
    for (int q = 0; q < 4; q++)
        d4[h*4 + q] = make_uint4(hv[4*q], hv[4*q+1], hv[4*q+2], hv[4*q+3]);
}

// ---------------- K3: conv dil=1  t1 -> h3 rows (fp16) -----------------------
__global__ __launch_bounds__(256, 3) void k_conv1(const float* __restrict__ bg) {
    extern __shared__ char smem[];
    unsigned sbase = smem_u32(smem);
    float* sbias = (float*)(smem + CSM_B2);
    int tid = threadIdx.x;
    int bx = blockIdx.x;
    int y  = bx >> 1;
    int x0 = (bx & 1) << 7;
    int n  = blockIdx.y;
    if (tid < 64) sbias[tid] = bg[tid];
    const size_t nb = (size_t)n * PPIX;

    conv_main<1>(g_t1, g_w1m, smem, sbase, y, x0, nb);

    const float* sd = (const float*)smem;
    int px = tid >> 1, h = tid & 1;
    const float* r = sd + px * 65;
    unsigned hv[16];
#pragma unroll
    for (int j = 0; j < 16; j++) {
        int oc = h * 32 + 2 * j;
        __half2 hh = __floats2half2_rn(fmaxf(r[oc]     + sbias[oc],     0.f),
                                       fmaxf(r[oc + 1] + sbias[oc + 1], 0.f));
        hv[j] = *(unsigned*)&hh;
    }
    uint4* d4 = (uint4*)(g_h1h + ((size_t)n * NPIX + y * WW + x0 + px) * HID);
#pragma unroll
    for (int q = 0; q < 4; q++)
        d4[h*4 + q] = make_uint4(hv[4*q], hv[4*q+1], hv[4*q+2], hv[4*q+3]);
}

// ---------------- K4: lang = log_softmax(relu(a@w1+b1)@w2+b2) -------------
__global__ void k_lang(const float* __restrict__ act,
                       const float* __restrict__ w1, const float* __restrict__ b1,
                       const float* __restrict__ w2, const float* __restrict__ b2) {
    int n = blockIdx.x;
    int t = threadIdx.x;      // 64 threads
    __shared__ float sh[HID];
    __shared__ float sz[KK2];
    __shared__ float slse;

    float acc = b1[t];
    for (int i = 0; i < AA; i++) acc = fmaf(act[n * AA + i], w1[i * HID + t], acc);
    sh[t] = fmaxf(acc, 0.f);
    __syncthreads();

    if (t < KK2) {
        float z = b2[t];
        for (int j = 0; j < HID; j++) z = fmaf(sh[j], w2[j * KK2 + t], z);
        sz[t] = z;
    }
    __syncthreads();
    if (t == 0) {
        float m = -1e30f;
        for (int k = 0; k < KK2; k++) m = fmaxf(m, sz[k]);
        float s = 0.f;
        for (int k = 0; k < KK2; k++) s += __expf(sz[k] - m);
        slse = m + __logf(s);
    }
    __syncthreads();
    if (t < KK2) g_lang[n * KK2 + t] = sz[t] - slse;
}

// ---------------- K5: x2 = x + b_out + W_out h3  (thin GEMV kernel) ---------
__global__ __launch_bounds__(256) void k_x2(const float* __restrict__ b_out) {
    __shared__ ull   swo2[HID * 16];
    __shared__ float sbo[DC];
    for (int i = threadIdx.x; i < HID * 16; i += 256) swo2[i] = g_wo[i];
    if (threadIdx.x < DC) sbo[threadIdx.x] = b_out[threadIdx.x];
    __syncthreads();

    int p   = blockIdx.x * 256 + threadIdx.x;
    int n   = p >> 16;
    int pix = p & (NPIX - 1);

    ull x22[16];
    const float* xb = g_x + (size_t)n * DC * NPIX + pix;
#pragma unroll
    for (int cc = 0; cc < 16; cc++)
        x22[cc] = pack2(xb[(size_t)(2*cc)*NPIX]   + sbo[2*cc],
                        xb[(size_t)(2*cc+1)*NPIX] + sbo[2*cc+1]);

    const uint4* hsrc = (const uint4*)(g_h1h + (size_t)p * HID);
#pragma unroll
    for (int q = 0; q < 8; q++) {
        uint4 hb = hsrc[q];
        const unsigned* hw = (const unsigned*)&hb;
#pragma unroll
        for (int j = 0; j < 4; j++) {
            __half2 hh = *(const __half2*)&hw[j];
            float2 f = __half22float2(hh);
            int ic = q * 8 + j * 2;
            ull hp0 = pack2(f.x, f.x);
#pragma unroll
            for (int cc = 0; cc < 16; cc++) ffma2(x22[cc], swo2[ic*16 + cc], hp0);
            ull hp1 = pack2(f.y, f.y);
#pragma unroll
            for (int cc = 0; cc < 16; cc++) ffma2(x22[cc], swo2[(ic+1)*16 + cc], hp1);
        }
    }

    float* xo = g_x2 + (size_t)n * DC * NPIX + pix;
#pragma unroll
    for (int cc = 0; cc < 16; cc++) {
        float lo, hi; unpack2(x22[cc], lo, hi);
        xo[(size_t)(2*cc)   * NPIX] = lo;
        xo[(size_t)(2*cc+1) * NPIX] = hi;
    }
}

// ---------------- K6: z = W_k x2 + b_k + lang; u' planes --------------------
__global__ __launch_bounds__(256) void k_zs(const float* __restrict__ b_k,
                                            const float* __restrict__ lb) {
    __shared__ ull   swk2[DC * 25];
    __shared__ float sbk[KK2];
    for (int i = threadIdx.x; i < DC * 25; i += 256) swk2[i] = g_wk[i];
    if (threadIdx.x < KK2) sbk[threadIdx.x] = b_k[threadIdx.x];
    __syncthreads();

    int p   = blockIdx.x * 256 + threadIdx.x;
    int n   = p >> 16;
    int pix = p & (NPIX - 1);

    const float* lg = g_lang + n * KK2;
    ull z2[25];
#pragma unroll
    for (int kk = 0; kk < 24; kk++)
        z2[kk] = pack2(sbk[2*kk]   + __ldg(&lg[2*kk]),
                       sbk[2*kk+1] + __ldg(&lg[2*kk+1]));
    z2[24] = pack2(sbk[48] + __ldg(&lg[48]), -1e4f);

    const float* xb = g_x2 + (size_t)n * DC * NPIX + pix;
#pragma unroll
    for (int c = 0; c < DC; c++) {
        float xv = xb[(size_t)c * NPIX];
        ull xp = pack2(xv, xv);
#pragma unroll
        for (int kk = 0; kk < 25; kk++) ffma2(z2[kk], swk2[c*25 + kk], xp);
    }

    float m = -1e30f;
#pragma unroll
    for (int kk = 0; kk < 25; kk++) {
        float a, b2v; unpack2(z2[kk], a, b2v);
        m = fmaxf(m, fmaxf(a, b2v));
    }

    float s = 0.f;
#pragma unroll
    for (int kk = 0; kk < 25; kk++) {
        float a, b2v; unpack2(z2[kk], a, b2v);
        float ua = fexp(a - m);
        float ubv = (kk < 24) ? fexp(b2v - m) : 0.f;
        s += ua + ubv;
        z2[kk] = pack2(ua, ubv);
    }
    float scale = __fdividef(fexp(lb[p]), s);

    int y = pix >> 8, x = pix & 255;
    float* ubp = g_u + (size_t)n * KK2 * UPP + (size_t)(y + 3) * UROW + (x + 3);
#pragma unroll
    for (int kk = 0; kk < 25; kk++) {
        float a, b2v; unpack2(z2[kk], a, b2v);
        ubp[(size_t)(2*kk) * UPP] = a * scale;
        if (kk < 24) ubp[(size_t)(2*kk+1) * UPP] = b2v * scale;
    }
}

// ---------------- K7: gather sum (scalar, padded planes, no predicates) ----
__global__ __launch_bounds__(256) void k_gather(float* __restrict__ out) {
    int p   = blockIdx.x * 256 + threadIdx.x;
    int n   = p >> 16;
    int pix = p & (NPIX - 1);
    int y = pix >> 8;
    int x = pix & (WW - 1);

    const float* ub = g_u + (size_t)n * KK2 * UPP;
    float s = 0.f;
#pragma unroll
    for (int ki = 0; ki < KW; ki++) {
        int rb = (y + 6 - ki) * UROW + x + 6;
#pragma unroll
        for (int kj = 0; kj < KW; kj++)
            s += ub[(size_t)(ki * KW + kj) * UPP + rb - kj];
    }
    out[p] = __logf(s);
}

// ---------------- launch ---------------------------------------------------
extern "C" void kernel_launch(void* const* d_in, const int* in_sizes, int n_in,
                              void* d_out, int out_size) {
    const float* log_belief = (const float*)d_in[0];
    const float* semantic   = (const float*)d_in[1];
    const float* action     = (const float*)d_in[2];
    const float* w_in  = (const float*)d_in[3];
    const float* b_in  = (const float*)d_in[4];
    const float* w_d3  = (const float*)d_in[5];
    const float* b_d3  = (const float*)d_in[6];
    const float* w_d1  = (const float*)d_in[7];
    const float* b_d1  = (const float*)d_in[8];
    const float* w_out = (const float*)d_in[9];
    const float* b_out = (const float*)d_in[10];
    const float* w_k   = (const float*)d_in[11];
    const float* b_k   = (const float*)d_in[12];
    const float* w_a1  = (const float*)d_in[13];
    const float* b_a1  = (const float*)d_in[14];
    const float* w_a2  = (const float*)d_in[15];
    const float* b_a2  = (const float*)d_in[16];
    float* out = (float*)d_out;

    cudaFuncSetAttribute(k_conv3,
                         cudaFuncAttributeMaxDynamicSharedMemorySize, CSMEM2);
    cudaFuncSetAttribute(k_conv1,
                         cudaFuncAttributeMaxDynamicSharedMemorySize, CSMEM2);

    // launch index 3 = k_conv1 (profiled): verify fp16 epilogue effect
    k_prep<<<300, 256>>>(w_d3, w_d1, w_in, w_out, w_k);              // 0
    k_pool_in<<<(NB * NPIX) / 256, 256>>>(semantic, b_in);           // 1

    dim3 cgrid(2 * HH, NB);
    k_conv3<<<cgrid, 256, CSMEM2>>>(b_d3);                           // 2
    k_conv1<<<cgrid, 256, CSMEM2>>>(b_d1);                           // 3

    k_lang<<<NB, 64>>>(action, w_a1, b_a1, w_a2, b_a2);              // 4
    k_x2<<<(NB * NPIX) / 256, 256>>>(b_out);                         // 5
    k_zs<<<(NB * NPIX) / 256, 256>>>(b_k, log_belief);               // 6
    k_gather<<<(NB * NPIX) / 256, 256>>>(out);                       // 7
}

// round 17
// speedup vs baseline: 1.0436x; 1.0436x over previous
#include <cuda_runtime.h>
#include <cuda_fp16.h>
#include <math.h>

#define NB   8
#define DC   32
#define HS   512
#define WSZ  512
#define HH   256
#define WW   256
#define KW   7
#define KK2  49
#define HID  64
#define AA   256
#define NPIX 65536          // HH*WW
#define PADW 262
#define PPIX (PADW*PADW)    // 68644  (fp16 activation pad)
#define UROW 264
#define UPP  (262*UROW)     // u' plane: 262 rows x 264 cols

typedef unsigned long long ull;

// ---------------- scratch (device globals; zero-initialized by CUDA) -------
// Pads of g_u / g_t0 / g_t1 are NEVER written -> stay zero.
__device__ __align__(256) float g_x  [NB * DC  * NPIX];
__device__ __align__(256) float g_u  [NB * KK2 * UPP];
__device__ __align__(256) float g_lang[NB * KK2];
__device__ __align__(256) __half g_h1h[(size_t)NB * NPIX * HID]; // h3 rows fp16

// transposed zero-padded activations: [n][pixpad][64] fp16
__device__ __align__(256) __half g_t0[(size_t)NB * PPIX * 64];
__device__ __align__(256) __half g_t1[(size_t)NB * PPIX * 64];

// conv weights: [tap][oc][64] fp16
__device__ __align__(256) __half g_w3m[9 * 64 * 64];
__device__ __align__(256) __half g_w1m[9 * 64 * 64];

// packed f32x2 weights for pointwise kernels
__device__ __align__(16) ull g_wi[DC * 32];
__device__ __align__(16) ull g_wo[HID * 16];
__device__ __align__(16) ull g_wk[DC * 25];

// ---------------- f32x2 helpers -------------------------------------------
__device__ __forceinline__ ull pack2(float lo, float hi) {
    ull r; asm("mov.b64 %0, {%1, %2};" : "=l"(r) : "f"(lo), "f"(hi)); return r;
}
__device__ __forceinline__ void unpack2(ull v, float& lo, float& hi) {
    asm("mov.b64 {%0, %1}, %2;" : "=f"(lo), "=f"(hi) : "l"(v));
}
__device__ __forceinline__ void ffma2(ull& d, ull a, ull b) {
    asm("fma.rn.f32x2 %0, %1, %2, %0;" : "+l"(d) : "l"(a), "l"(b));
}
__device__ __forceinline__ float fexp(float x) {
    float t  = fmaxf(x * 1.44269504f, -120.f);
    float rv = rintf(t);
    int   e  = (int)rv;
    float f  = t - rv;
    float p  = 1.33335581e-3f;
    p = fmaf(p, f, 9.61812910e-3f);
    p = fmaf(p, f, 5.55041087e-2f);
    p = fmaf(p, f, 2.40226507e-1f);
    p = fmaf(p, f, 6.93147181e-1f);
    p = fmaf(p, f, 1.0f);
    return __int_as_float(__float_as_int(p) + (e << 23));
}

// ---------------- tensor-core + async helpers (sm_80 baseline) -------------
__device__ __forceinline__ unsigned smem_u32(const void* p) {
    unsigned a;
    asm("{ .reg .u64 t; cvta.to.shared.u64 t, %1; cvt.u32.u64 %0, t; }"
        : "=r"(a) : "l"(p));
    return a;
}
__device__ __forceinline__ void ldsm4(unsigned& r0, unsigned& r1,
                                      unsigned& r2, unsigned& r3, unsigned addr) {
    asm volatile("ldmatrix.sync.aligned.m8n8.x4.shared.b16 {%0,%1,%2,%3}, [%4];"
                 : "=r"(r0), "=r"(r1), "=r"(r2), "=r"(r3) : "r"(addr));
}
__device__ __forceinline__ void mma16816(float* c, const unsigned* a,
                                         unsigned b0, unsigned b1) {
    asm volatile(
        "mma.sync.aligned.m16n8k16.row.col.f32.f16.f16.f32 "
        "{%0,%1,%2,%3}, {%4,%5,%6,%7}, {%8,%9}, {%0,%1,%2,%3};"
        : "+f"(c[0]), "+f"(c[1]), "+f"(c[2]), "+f"(c[3])
        : "r"(a[0]), "r"(a[1]), "r"(a[2]), "r"(a[3]), "r"(b0), "r"(b1));
}
__device__ __forceinline__ void cpasync16(unsigned dst, const void* src) {
    asm volatile("cp.async.ca.shared.global [%0], [%1], 16;"
                 :: "r"(dst), "l"(src));
}
#define CP_COMMIT() asm volatile("cp.async.commit_group;" ::: "memory")
#define CP_WAIT0()  asm volatile("cp.async.wait_group 0;" ::: "memory")

// ---------------- K0: weight packing only ----------------------------------
__global__ void k_prep(const float* __restrict__ w_d3, const float* __restrict__ w_d1,
                       const float* __restrict__ w_in, const float* __restrict__ w_out,
                       const float* __restrict__ w_k) {
    int i = blockIdx.x * 256 + threadIdx.x;
    if (i < 36864) {
        int ic = i & 63, oc = (i >> 6) & 63, tap = i >> 12;
        g_w3m[i] = __float2half_rn(w_d3[((size_t)oc * HID + ic) * 9 + tap]);
    } else if (i < 73728) {
        int q = i - 36864;
        int ic = q & 63, oc = (q >> 6) & 63, tap = q >> 12;
        g_w1m[q] = __float2half_rn(w_d1[((size_t)oc * HID + ic) * 9 + tap]);
    } else if (i < 74752) {
        int q = i - 73728; int c = q >> 5, j = q & 31;
        g_wi[q] = pack2(w_in[(2*j)*DC + c], w_in[(2*j+1)*DC + c]);
    } else if (i < 75776) {
        int q = i - 74752; int ic = q >> 4, cc = q & 15;
        g_wo[q] = pack2(w_out[(2*cc)*HID + ic], w_out[(2*cc+1)*HID + ic]);
    } else if (i < 76576) {
        int q = i - 75776; int c = q / 25, kk = q % 25;
        float w1v = (2*kk + 1 < KK2) ? w_k[(2*kk+1)*DC + c] : 0.f;
        g_wk[q] = pack2(w_k[(2*kk)*DC + c], w1v);
    }
}

// ---------------- K1: FUSED 2x2 max pool + conv1x1 32->64 + relu ------------
__global__ __launch_bounds__(256, 2) void k_pool_in(const float* __restrict__ sem,
                                                    const float* __restrict__ b) {
    __shared__ ull   sw2[DC * 32];
    __shared__ float sb[HID];
    for (int i = threadIdx.x; i < DC * 32; i += 256) sw2[i] = g_wi[i];
    if (threadIdx.x < HID) sb[threadIdx.x] = b[threadIdx.x];
    __syncthreads();

    int p   = blockIdx.x * 256 + threadIdx.x;
    int n   = p >> 16;
    int pix = p & (NPIX - 1);
    int y = pix >> 8, x = pix & 255;

    float xv[DC];
    const float* base = sem + ((size_t)n * DC) * HS * WSZ
                        + (size_t)(2 * y) * WSZ + 2 * x;
#pragma unroll
    for (int c = 0; c < DC; c++) {
        const float2* r0 = (const float2*)(base + (size_t)c * HS * WSZ);
        const float2* r1 = (const float2*)(base + (size_t)c * HS * WSZ + WSZ);
        float2 a = r0[0];
        float2 bb = r1[0];
        xv[c] = fmaxf(fmaxf(a.x, a.y), fmaxf(bb.x, bb.y));
    }

    float* xo = g_x + (size_t)n * DC * NPIX + pix;
#pragma unroll
    for (int c = 0; c < DC; c++) xo[(size_t)c * NPIX] = xv[c];

    uint4* d4 = (uint4*)(g_t0 + ((size_t)n * PPIX + (size_t)(y + 3) * PADW + (x + 3)) * 64);
#pragma unroll
    for (int half = 0; half < 2; half++) {
        int off = half * 16;
        ull acc[16];
#pragma unroll
        for (int j = 0; j < 16; j++)
            acc[j] = pack2(sb[half*32 + 2*j], sb[half*32 + 2*j + 1]);
#pragma unroll
        for (int c = 0; c < DC; c++) {
            ull xp = pack2(xv[c], xv[c]);
#pragma unroll
            for (int j = 0; j < 16; j++) ffma2(acc[j], sw2[c*32 + off + j], xp);
        }
        unsigned hv[16];
#pragma unroll
        for (int j = 0; j < 16; j++) {
            float v0, v1; unpack2(acc[j], v0, v1);
            __half2 hh = __floats2half2_rn(fmaxf(v0, 0.f), fmaxf(v1, 0.f));
            hv[j] = *(unsigned*)&hh;
        }
#pragma unroll
        for (int q = 0; q < 4; q++)
            d4[half*4 + q] = make_uint4(hv[4*q], hv[4*q+1], hv[4*q+2], hv[4*q+3]);
    }
}

// ---------------- conv3x3 mainloop (fp16 K=64, 32x32 warp tiles) ------------
#define ASLOT   17152
#define WOFF2   34304
#define CSM_B2  50688
#define CSMEM2  50944

template <int DIL>
__device__ __forceinline__ void conv_main(const __half* __restrict__ tin,
                                          const __half* __restrict__ wgt,
                                          char* smem, unsigned sbase,
                                          int y, int x0, size_t nb) {
    constexpr int NSPH = 128 + 2 * DIL;
    int tid = threadIdx.x, lane = tid & 31, w = tid >> 5;
    int wm = w & 3, wn = w >> 2;           // 4 x 2 warp grid

    auto stage_A = [&](int ky, int slot, int part) {
        int ypad = y + (ky - 1) * DIL + 3;
        const __half* src =
            tin + (nb + (size_t)ypad * PADW + (3 + x0 - DIL)) * 64;
        int lo = (part == 1) ? (NSPH * 8) / 2 : 0;
        int hi = (part == 0) ? (NSPH * 8) / 2 : NSPH * 8;
        for (int i = lo + tid; i < hi; i += 256) {
            int sp = i >> 3, seg = i & 7;
            unsigned rel = sp * 128 + ((seg << 4) ^ ((sp & 7) << 4));
            cpasync16(sbase + slot * ASLOT + rel, src + sp * 64 + seg * 8);
        }
    };
    auto stage_W = [&](int tap, int slot) {
        const __half* ws = wgt + (size_t)tap * 64 * 64;
#pragma unroll
        for (int k = 0; k < 2; k++) {
            int i = tid + k * 256;
            int oc = i >> 3, seg = i & 7;
            unsigned rel = oc * 128 + ((seg << 4) ^ ((oc & 7) << 4));
            cpasync16(sbase + WOFF2 + slot * 8192 + rel, ws + oc * 64 + seg * 8);
        }
    };

    float acc[2][4][4];
#pragma unroll
    for (int a = 0; a < 2; a++)
#pragma unroll
        for (int b2 = 0; b2 < 4; b2++)
#pragma unroll
            for (int c = 0; c < 4; c++) acc[a][b2][c] = 0.f;

    const int akoff = ((lane >> 4) & 1) << 4;
    const int bkoff = ((lane >> 3) & 1) << 4;

    stage_A(0, 0, 2);
    stage_W(0, 0);
    CP_COMMIT();
    CP_WAIT0();
    __syncthreads();

#pragma unroll
    for (int t = 0; t < 9; t++) {
        const int ky = t / 3, kx = t % 3;
        const int wslot = t & 1;
        const int aslot = ky & 1;

        if (t < 8) {
            stage_W(t + 1, wslot ^ 1);
            if (kx < 2 && ky < 2) stage_A(ky + 1, aslot ^ 1, kx);
            CP_COMMIT();
        }

        unsigned arow[2], arx[2];
#pragma unroll
        for (int mt = 0; mt < 2; mt++) {
            int px = wm * 32 + mt * 16 + ((lane >> 3) & 1) * 8 + (lane & 7);
            int sp = px + kx * DIL;
            arow[mt] = sbase + aslot * ASLOT + sp * 128;
            arx[mt]  = (sp & 7) << 4;
        }
        unsigned Wb = sbase + WOFF2 + wslot * 8192;
        unsigned brow[2], brx[2];
#pragma unroll
        for (int j = 0; j < 2; j++) {
            int ocb = wn * 32 + j * 16 + ((lane >> 4) & 1) * 8 + (lane & 7);
            brow[j] = Wb + ocb * 128;
            brx[j]  = (ocb & 7) << 4;
        }

#pragma unroll
        for (int kc = 0; kc < 4; kc++) {
            unsigned a[2][4];
#pragma unroll
            for (int mt = 0; mt < 2; mt++)
                ldsm4(a[mt][0], a[mt][1], a[mt][2], a[mt][3],
                      arow[mt] + (unsigned)((kc * 32 + akoff) ^ arx[mt]));
            unsigned b[2][4];
#pragma unroll
            for (int j = 0; j < 2; j++)
                ldsm4(b[j][0], b[j][1], b[j][2], b[j][3],
                      brow[j] + (unsigned)((kc * 32 + bkoff) ^ brx[j]));
#pragma unroll
            for (int mt = 0; mt < 2; mt++)
#pragma unroll
                for (int nt = 0; nt < 4; nt++)
                    mma16816(acc[mt][nt], a[mt],
                             b[nt >> 1][(nt & 1) * 2],
                             b[nt >> 1][(nt & 1) * 2 + 1]);
        }

        CP_WAIT0();
        __syncthreads();
    }

    float* sd = (float*)smem;
#pragma unroll
    for (int mt = 0; mt < 2; mt++)
#pragma unroll
        for (int nt = 0; nt < 4; nt++)
#pragma unroll
            for (int c = 0; c < 4; c++) {
                int px = wm * 32 + mt * 16 + (lane >> 2) + ((c >> 1) & 1) * 8;
                int oc = wn * 32 + nt * 8 + 2 * (lane & 3) + (c & 1);
                sd[px * 65 + oc] = acc[mt][nt][c];
            }
    __syncthreads();
}

// ---------------- K2: conv dil=3  t0 -> t1 (fp16) ---------------------------
__global__ __launch_bounds__(256, 3) void k_conv3(const float* __restrict__ bg) {
    extern __shared__ char smem[];
    unsigned sbase = smem_u32(smem);
    float* sbias = (float*)(smem + CSM_B2);
    int tid = threadIdx.x;
    int bx = blockIdx.x;
    int y  = bx >> 1;
    int x0 = (bx & 1) << 7;
    int n  = blockIdx.y;
    if (tid < 64) sbias[tid] = bg[tid];
    const size_t nb = (size_t)n * PPIX;

    conv_main<3>(g_t0, g_w3m, smem, sbase, y, x0, nb);

    const float* sd = (const float*)smem;
    int px = tid >> 1, h = tid & 1;
    const float* r = sd + px * 65;
    unsigned hv[16];
#pragma unroll
    for (int j = 0; j < 16; j++) {
        int oc = h * 32 + 2 * j;
        __half2 hh = __floats2half2_rn(fmaxf(r[oc]     + sbias[oc],     0.f),
                                       fmaxf(r[oc + 1] + sbias[oc + 1], 0.f));
        hv[j] = *(unsigned*)&hh;
    }
    uint4* d4 = (uint4*)(g_t1 + (nb + (size_t)(y + 3) * PADW + (x0 + px + 3)) * 64);
#pragma unroll
    for (int q = 0; q < 4; q++)
        d4[h*4 + q] = make_uint4(hv[4*q], hv[4*q+1], hv[4*q+2], hv[4*q+3]);
}

// ---------------- K3: conv dil=1  t1 -> h3 rows (fp16) -----------------------
__global__ __launch_bounds__(256, 3) void k_conv1(const float* __restrict__ bg) {
    extern __shared__ char smem[];
    unsigned sbase = smem_u32(smem);
    float* sbias = (float*)(smem + CSM_B2);
    int tid = threadIdx.x;
    int bx = blockIdx.x;
    int y  = bx >> 1;
    int x0 = (bx & 1) << 7;
    int n  = blockIdx.y;
    if (tid < 64) sbias[tid] = bg[tid];
    const size_t nb = (size_t)n * PPIX;

    conv_main<1>(g_t1, g_w1m, smem, sbase, y, x0, nb);

    const float* sd = (const float*)smem;
    int px = tid >> 1, h = tid & 1;
    const float* r = sd + px * 65;
    unsigned hv[16];
#pragma unroll
    for (int j = 0; j < 16; j++) {
        int oc = h * 32 + 2 * j;
        __half2 hh = __floats2half2_rn(fmaxf(r[oc]     + sbias[oc],     0.f),
                                       fmaxf(r[oc + 1] + sbias[oc + 1], 0.f));
        hv[j] = *(unsigned*)&hh;
    }
    uint4* d4 = (uint4*)(g_h1h + ((size_t)n * NPIX + y * WW + x0 + px) * HID);
#pragma unroll
    for (int q = 0; q < 4; q++)
        d4[h*4 + q] = make_uint4(hv[4*q], hv[4*q+1], hv[4*q+2], hv[4*q+3]);
}

// ---------------- K4: lang = log_softmax(relu(a@w1+b1)@w2+b2) -------------
__global__ void k_lang(const float* __restrict__ act,
                       const float* __restrict__ w1, const float* __restrict__ b1,
                       const float* __restrict__ w2, const float* __restrict__ b2) {
    int n = blockIdx.x;
    int t = threadIdx.x;      // 64 threads
    __shared__ float sh[HID];
    __shared__ float sz[KK2];
    __shared__ float slse;

    float acc = b1[t];
    for (int i = 0; i < AA; i++) acc = fmaf(act[n * AA + i], w1[i * HID + t], acc);
    sh[t] = fmaxf(acc, 0.f);
    __syncthreads();

    if (t < KK2) {
        float z = b2[t];
        for (int j = 0; j < HID; j++) z = fmaf(sh[j], w2[j * KK2 + t], z);
        sz[t] = z;
    }
    __syncthreads();
    if (t == 0) {
        float m = -1e30f;
        for (int k = 0; k < KK2; k++) m = fmaxf(m, sz[k]);
        float s = 0.f;
        for (int k = 0; k < KK2; k++) s += __expf(sz[k] - m);
        slse = m + __logf(s);
    }
    __syncthreads();
    if (t < KK2) g_lang[n * KK2 + t] = sz[t] - slse;
}

// ---- K5: fused motion (single kernel, fp16 h3 reads) -----------------------
__global__ __launch_bounds__(256) void k_motion(const float* __restrict__ b_out,
                                                const float* __restrict__ b_k,
                                                const float* __restrict__ lb) {
    __shared__ ull   swo2[HID * 16];
    __shared__ ull   swk2[DC * 25];
    __shared__ float sbo[DC];
    __shared__ float sbk[KK2];
    for (int i = threadIdx.x; i < HID * 16; i += 256) swo2[i] = g_wo[i];
    for (int i = threadIdx.x; i < DC * 25;  i += 256) swk2[i] = g_wk[i];
    if (threadIdx.x < DC)  sbo[threadIdx.x] = b_out[threadIdx.x];
    if (threadIdx.x < KK2) sbk[threadIdx.x] = b_k[threadIdx.x];
    __syncthreads();

    int p   = blockIdx.x * 256 + threadIdx.x;
    int n   = p >> 16;
    int pix = p & (NPIX - 1);

    ull x22[16];
    const float* xb = g_x + (size_t)n * DC * NPIX + pix;
#pragma unroll
    for (int cc = 0; cc < 16; cc++)
        x22[cc] = pack2(xb[(size_t)(2*cc)*NPIX]   + sbo[2*cc],
                        xb[(size_t)(2*cc+1)*NPIX] + sbo[2*cc+1]);

    const uint4* hsrc = (const uint4*)(g_h1h + (size_t)p * HID);
#pragma unroll
    for (int q = 0; q < 8; q++) {
        uint4 hb = hsrc[q];
        const unsigned* hw = (const unsigned*)&hb;
#pragma unroll
        for (int j = 0; j < 4; j++) {
            __half2 hh = *(const __half2*)&hw[j];
            float2 f = __half22float2(hh);
            int ic = q * 8 + j * 2;
            ull hp0 = pack2(f.x, f.x);
#pragma unroll
            for (int cc = 0; cc < 16; cc++) ffma2(x22[cc], swo2[ic*16 + cc], hp0);
            ull hp1 = pack2(f.y, f.y);
#pragma unroll
            for (int cc = 0; cc < 16; cc++) ffma2(x22[cc], swo2[(ic+1)*16 + cc], hp1);
        }
    }

    const float* lg = g_lang + n * KK2;
    ull z2[25];
#pragma unroll
    for (int kk = 0; kk < 24; kk++)
        z2[kk] = pack2(sbk[2*kk]   + __ldg(&lg[2*kk]),
                       sbk[2*kk+1] + __ldg(&lg[2*kk+1]));
    z2[24] = pack2(sbk[48] + __ldg(&lg[48]), -1e4f);

#pragma unroll
    for (int cc = 0; cc < 16; cc++) {
        float x0, x1; unpack2(x22[cc], x0, x1);
        ull xp0 = pack2(x0, x0);
#pragma unroll
        for (int kk = 0; kk < 25; kk++) ffma2(z2[kk], swk2[(2*cc)*25 + kk], xp0);
        ull xp1 = pack2(x1, x1);
#pragma unroll
        for (int kk = 0; kk < 25; kk++) ffma2(z2[kk], swk2[(2*cc+1)*25 + kk], xp1);
    }

    float m = -1e30f;
#pragma unroll
    for (int kk = 0; kk < 25; kk++) {
        float a, b2v; unpack2(z2[kk], a, b2v);
        m = fmaxf(m, fmaxf(a, b2v));
    }

    float s = 0.f;
#pragma unroll
    for (int kk = 0; kk < 25; kk++) {
        float a, b2v; unpack2(z2[kk], a, b2v);
        float ua = fexp(a - m);
        float ubv = (kk < 24) ? fexp(b2v - m) : 0.f;
        s += ua + ubv;
        z2[kk] = pack2(ua, ubv);
    }
    float scale = __fdividef(fexp(lb[p]), s);

    int y = pix >> 8, x = pix & 255;
    float* ubp = g_u + (size_t)n * KK2 * UPP + (size_t)(y + 3) * UROW + (x + 3);
#pragma unroll
    for (int kk = 0; kk < 25; kk++) {
        float a, b2v; unpack2(z2[kk], a, b2v);
        ubp[(size_t)(2*kk) * UPP] = a * scale;
        if (kk < 24) ubp[(size_t)(2*kk+1) * UPP] = b2v * scale;
    }
}

// ---------------- K6: gather sum (scalar, padded planes, no predicates) ----
__global__ __launch_bounds__(256) void k_gather(float* __restrict__ out) {
    int p   = blockIdx.x * 256 + threadIdx.x;
    int n   = p >> 16;
    int pix = p & (NPIX - 1);
    int y = pix >> 8;
    int x = pix & (WW - 1);

    const float* ub = g_u + (size_t)n * KK2 * UPP;
    float s = 0.f;
#pragma unroll
    for (int ki = 0; ki < KW; ki++) {
        int rb = (y + 6 - ki) * UROW + x + 6;
#pragma unroll
        for (int kj = 0; kj < KW; kj++)
            s += ub[(size_t)(ki * KW + kj) * UPP + rb - kj];
    }
    out[p] = __logf(s);
}

// ---------------- launch ---------------------------------------------------
extern "C" void kernel_launch(void* const* d_in, const int* in_sizes, int n_in,
                              void* d_out, int out_size) {
    const float* log_belief = (const float*)d_in[0];
    const float* semantic   = (const float*)d_in[1];
    const float* action     = (const float*)d_in[2];
    const float* w_in  = (const float*)d_in[3];
    const float* b_in  = (const float*)d_in[4];
    const float* w_d3  = (const float*)d_in[5];
    const float* b_d3  = (const float*)d_in[6];
    const float* w_d1  = (const float*)d_in[7];
    const float* b_d1  = (const float*)d_in[8];
    const float* w_out = (const float*)d_in[9];
    const float* b_out = (const float*)d_in[10];
    const float* w_k   = (const float*)d_in[11];
    const float* b_k   = (const float*)d_in[12];
    const float* w_a1  = (const float*)d_in[13];
    const float* b_a1  = (const float*)d_in[14];
    const float* w_a2  = (const float*)d_in[15];
    const float* b_a2  = (const float*)d_in[16];
    float* out = (float*)d_out;

    cudaFuncSetAttribute(k_conv3,
                         cudaFuncAttributeMaxDynamicSharedMemorySize, CSMEM2);
    cudaFuncSetAttribute(k_conv1,
                         cudaFuncAttributeMaxDynamicSharedMemorySize, CSMEM2);

    // launch index 3 = k_conv1 (profiled sentinel)
    k_prep<<<300, 256>>>(w_d3, w_d1, w_in, w_out, w_k);              // 0
    k_pool_in<<<(NB * NPIX) / 256, 256>>>(semantic, b_in);           // 1

    dim3 cgrid(2 * HH, NB);
    k_conv3<<<cgrid, 256, CSMEM2>>>(b_d3);                           // 2
    k_conv1<<<cgrid, 256, CSMEM2>>>(b_d1);                           // 3

    k_lang<<<NB, 64>>>(action, w_a1, b_a1, w_a2, b_a2);              // 4
    k_motion<<<(NB * NPIX) / 256, 256>>>(b_out, b_k, log_belief);    // 5
    k_gather<<<(NB * NPIX) / 256, 256>>>(out);                       // 6
}